// round 4
// baseline (speedup 1.0000x reference)
#include <cuda_runtime.h>
#include <cstdint>

#define T_DIM 64
#define U_DIM 142
#define I_DIM 4500
#define ITEMS4 (I_DIM / 4)     // 1125, exact
#define B_DIM 16384
#define K_TOP 10
#define MASK_WORDS 5           // ceil(142/32)

// Scratch: rated bitmask per (t, i): 64*4500*5 u32 = 5.76 MB
__device__ uint32_t g_mask[(size_t)T_DIM * I_DIM * MASK_WORDS];

// ---------------------------------------------------------------------------
// Phase A: streaming scan of qos -> packed rated bitmask, float4 loads.
// Thread owns 4 consecutive items; loops over all 142 users with LDG.128.
// grid = (ceil(1125/256), 64). Writes 20 contiguous words/thread (coalesced).
// ---------------------------------------------------------------------------
__global__ __launch_bounds__(256) void mask_kernel(const float4* __restrict__ qos4)
{
    const int t  = blockIdx.y;
    const int i4 = blockIdx.x * 256 + threadIdx.x;
    if (i4 >= ITEMS4) return;

    const float4* base = qos4 + (size_t)t * U_DIM * ITEMS4 + i4;

    uint32_t m[4][MASK_WORDS];
    #pragma unroll
    for (int c = 0; c < 4; c++)
        #pragma unroll
        for (int w = 0; w < MASK_WORDS; w++) m[c][w] = 0u;

    #pragma unroll
    for (int w = 0; w < MASK_WORDS; w++) {
        const int nb = (w < 4) ? 32 : (U_DIM - 128);
        #pragma unroll
        for (int vb = 0; vb < 32; vb++) {
            if (vb < nb) {
                const int v = w * 32 + vb;
                const float4 q = __ldg(base + (size_t)v * ITEMS4);
                const uint32_t bit = 1u << vb;
                if (q.x > 0.f) m[0][w] |= bit;
                if (q.y > 0.f) m[1][w] |= bit;
                if (q.z > 0.f) m[2][w] |= bit;
                if (q.w > 0.f) m[3][w] |= bit;
            }
        }
    }

    // 20 contiguous words per thread; base byte offset divisible by 16.
    uint4* outp = (uint4*)(g_mask + ((size_t)t * I_DIM + 4 * (size_t)i4) * MASK_WORDS);
    outp[0] = make_uint4(m[0][0], m[0][1], m[0][2], m[0][3]);
    outp[1] = make_uint4(m[0][4], m[1][0], m[1][1], m[1][2]);
    outp[2] = make_uint4(m[1][3], m[1][4], m[2][0], m[2][1]);
    outp[3] = make_uint4(m[2][2], m[2][3], m[2][4], m[3][0]);
    outp[4] = make_uint4(m[3][1], m[3][2], m[3][3], m[3][4]);
}

// ---------------------------------------------------------------------------
// Phase B: one warp per batch element. u32 monotonic keys + REDUX warp max.
// Lane owns users v = lane + 32j (j<5).
// ---------------------------------------------------------------------------
__global__ __launch_bounds__(256) void predict_kernel(
    const float* __restrict__ qos,
    const float* __restrict__ user_avg,
    const float* __restrict__ sim,
    const int*   __restrict__ user_id,
    const int*   __restrict__ item_id,
    const int*   __restrict__ time_id,
    float*       __restrict__ out)
{
    const int warp = (blockIdx.x * blockDim.x + threadIdx.x) >> 5;
    const int lane = threadIdx.x & 31;
    if (warp >= B_DIM) return;

    const int t  = time_id[warp];
    const int u  = user_id[warp];
    const int it = item_id[warp];

    const uint32_t* mrow = g_mask + ((size_t)t * I_DIM + it) * MASK_WORDS;
    const uint32_t  mw   = (lane < MASK_WORDS) ? mrow[lane] : 0u;

    const float* srow = sim + u * U_DIM;    // 80 KB matrix: cache-resident

    // Keys: monotonic u32 of sim_m (rated -> sim, unrated -> 0.0).
    // Valid keys are >= 0x80000000 for sim_m >= 0, and > 0 always
    // (uniform(-1,1) sims map to > 0). Invalid slot sentinel = 0.
    uint32_t key[5];
    float    sv[5];
    #pragma unroll
    for (int j = 0; j < 5; j++) {
        const int v = lane + 32 * j;
        const uint32_t m = __shfl_sync(0xFFFFFFFFu, mw, j);
        const bool valid = (v < U_DIM);
        const bool rated = valid && ((m >> lane) & 1u);
        const float s  = valid ? __ldg(srow + v) : 0.f;
        const float sm = rated ? s : 0.f;
        sv[j] = sm;
        uint32_t b = __float_as_uint(sm);
        b = (b & 0x80000000u) ? ~b : (b | 0x80000000u);
        key[j] = valid ? b : 0u;
    }

    // 10 rounds: local max of 5, REDUX warp max, elect first matching lane,
    // clear ALL slots equal to gbest on that lane (duplicates only at
    // sim_m == 0.0, whose contribution is identically 0 -> exact).
    unsigned sel = 0;
    #pragma unroll 1
    for (int r = 0; r < K_TOP; r++) {
        uint32_t local = key[0];
        #pragma unroll
        for (int j = 1; j < 5; j++) local = max(local, key[j]);

        const uint32_t g = __reduce_max_sync(0xFFFFFFFFu, local);
        const unsigned bal = __ballot_sync(0xFFFFFFFFu, local == g);
        if (lane == (__ffs(bal) - 1)) {
            #pragma unroll
            for (int j = 0; j < 5; j++) {
                if (key[j] == g) { key[j] = 0u; sel |= (1u << j); }
            }
        }
    }

    // Gather qos / avg only for selected users (<= ~10 scattered sectors).
    float S = 0.f, P = 0.f;
    const float* qcol = qos + (size_t)t * U_DIM * I_DIM + it;
    const float* arow = user_avg + t * U_DIM;
    #pragma unroll
    for (int j = 0; j < 5; j++) {
        if (sel & (1u << j)) {
            const int v = lane + 32 * j;
            const float q  = __ldg(qcol + (size_t)v * I_DIM);
            const float av = __ldg(arow + v);
            const float s  = sv[j];
            S += s;
            P += s * (q - av);
        }
    }

    #pragma unroll
    for (int o = 16; o; o >>= 1) {
        S += __shfl_xor_sync(0xFFFFFFFFu, S, o);
        P += __shfl_xor_sync(0xFFFFFFFFu, P, o);
    }

    if (lane == 0) {
        const float avg_u = __ldg(arow + u);
        out[warp] = avg_u + P / (S + 1e-8f);
    }
}

// ---------------------------------------------------------------------------
extern "C" void kernel_launch(void* const* d_in, const int* in_sizes, int n_in,
                              void* d_out, int out_size) {
    const float* qos      = (const float*)d_in[0];  // [T,U,I]
    const float* user_avg = (const float*)d_in[1];  // [T,U]
    const float* sim      = (const float*)d_in[2];  // [U,U]
    const int*   user_id  = (const int*)d_in[3];    // [B]
    const int*   item_id  = (const int*)d_in[4];    // [B]
    const int*   time_id  = (const int*)d_in[5];    // [B]
    float* out = (float*)d_out;

    dim3 gridA((ITEMS4 + 255) / 256, T_DIM);        // 5 x 64 = 320 CTAs
    mask_kernel<<<gridA, 256>>>((const float4*)qos);

    predict_kernel<<<(B_DIM * 32) / 256, 256>>>(qos, user_avg, sim,
                                                user_id, item_id, time_id, out);
}

// round 5
// speedup vs baseline: 1.1454x; 1.1454x over previous
#include <cuda_runtime.h>
#include <cstdint>

#define T_DIM 64
#define U_DIM 142
#define I_DIM 4500
#define ITEMS4 (I_DIM / 4)     // 1125 exact
#define B_DIM 16384
#define K_TOP 10
#define MASK_WORDS 5           // ceil(142/32)
#define PREFETCH 24            // sorted entries prefetched per element

// Planar rated-bitmask: g_maskp[w][t*I + i]. 5 x 288000 x 4B = 5.76 MB.
__device__ uint32_t g_maskp[MASK_WORDS][(size_t)T_DIM * I_DIM];
// Per-user argsort of sim row, descending, tie -> lower index first.
// Entry: (float bits << 32) | user index. 142*142*8B = 161 KB.
__device__ unsigned long long g_sorted[U_DIM * U_DIM];

// ---------------------------------------------------------------------------
// Phase A: streaming qos scan -> planar bitmask.
// grid = (ceil(1125/128)=9, T=64, W=5), block = 128.
// CTA (x,t,w): packs mask word w (users w*32 .. w*32+nb) for items
// [x*512, x*512+512). Thread owns 4 consecutive items (float4 loads).
// ---------------------------------------------------------------------------
__global__ __launch_bounds__(128) void mask_kernel(const float4* __restrict__ qos4)
{
    const int w  = blockIdx.z;
    const int t  = blockIdx.y;
    const int i4 = blockIdx.x * 128 + threadIdx.x;
    if (i4 >= ITEMS4) return;

    const float4* base = qos4 + ((size_t)t * U_DIM + w * 32) * ITEMS4 + i4;

    uint32_t m0 = 0, m1 = 0, m2 = 0, m3 = 0;
    if (w < 4) {
        #pragma unroll
        for (int vb = 0; vb < 32; vb++) {
            const float4 q = __ldg(base + (size_t)vb * ITEMS4);
            const uint32_t bit = 1u << vb;
            if (q.x > 0.f) m0 |= bit;
            if (q.y > 0.f) m1 |= bit;
            if (q.z > 0.f) m2 |= bit;
            if (q.w > 0.f) m3 |= bit;
        }
    } else {
        #pragma unroll
        for (int vb = 0; vb < (U_DIM - 128); vb++) {   // 14 users
            const float4 q = __ldg(base + (size_t)vb * ITEMS4);
            const uint32_t bit = 1u << vb;
            if (q.x > 0.f) m0 |= bit;
            if (q.y > 0.f) m1 |= bit;
            if (q.z > 0.f) m2 |= bit;
            if (q.w > 0.f) m3 |= bit;
        }
    }

    // Coalesced uint4 store into plane w.
    *(uint4*)(&g_maskp[w][(size_t)t * I_DIM + 4 * (size_t)i4]) =
        make_uint4(m0, m1, m2, m3);
}

// ---------------------------------------------------------------------------
// Argsort of each sim row (descending, stable by index). One CTA per user u.
// rank(v) = #{w : s[w] > s[v]  or  (s[w] == s[v] and w < v)}  -> permutation.
// ---------------------------------------------------------------------------
__global__ __launch_bounds__(160) void sort_kernel(const float* __restrict__ sim)
{
    const int u = blockIdx.x;
    const int v = threadIdx.x;
    __shared__ float row[U_DIM];
    if (v < U_DIM) row[v] = sim[u * U_DIM + v];
    __syncthreads();
    if (v >= U_DIM) return;

    const float sv = row[v];
    int rank = 0;
    #pragma unroll 2
    for (int w = 0; w < U_DIM; w++) {
        const float sw = row[w];
        rank += (sw > sv) || (sw == sv && w < v);
    }
    g_sorted[u * U_DIM + rank] =
        ((unsigned long long)__float_as_uint(sv) << 32) | (unsigned)v;
}

// ---------------------------------------------------------------------------
// Phase B: one THREAD per batch element. Walk the descending sim order,
// take rated entries while sim > 0, up to K_TOP. (Unrated zeros pad the
// reference's top-k with identically-zero contributions; negative rated sims
// rank below zeros and are never selected -> exact.)
// ---------------------------------------------------------------------------
__global__ __launch_bounds__(128) void predict_kernel(
    const float* __restrict__ qos,
    const float* __restrict__ user_avg,
    const int*   __restrict__ user_id,
    const int*   __restrict__ item_id,
    const int*   __restrict__ time_id,
    float*       __restrict__ out)
{
    const int b = blockIdx.x * blockDim.x + threadIdx.x;
    if (b >= B_DIM) return;

    const int t  = time_id[b];
    const int u  = user_id[b];
    const int it = item_id[b];

    const size_t ti = (size_t)t * I_DIM + it;
    // Mask as three 64-bit regs (avoids local-memory dynamic indexing).
    const unsigned long long m01 =
        (unsigned long long)g_maskp[0][ti] | ((unsigned long long)g_maskp[1][ti] << 32);
    const unsigned long long m23 =
        (unsigned long long)g_maskp[2][ti] | ((unsigned long long)g_maskp[3][ti] << 32);
    const unsigned long long m4 = (unsigned long long)g_maskp[4][ti];

    const unsigned long long* srt = g_sorted + u * U_DIM;
    const float* qcol = qos + (size_t)t * U_DIM * I_DIM + it;
    const float* arow = user_avg + t * U_DIM;

    // Prefetch first PREFETCH sorted entries with high MLP.
    unsigned long long e[PREFETCH];
    #pragma unroll
    for (int k = 0; k < PREFETCH; k += 2) {
        const ulonglong2 p = __ldg((const ulonglong2*)(srt + k));
        e[k] = p.x; e[k + 1] = p.y;
    }

    float S = 0.f, P = 0.f;
    int cnt = 0;
    bool live = true;

    #pragma unroll
    for (int k = 0; k < PREFETCH; k++) {
        const float s = __uint_as_float((unsigned)(e[k] >> 32));
        const int   v = (int)(e[k] & 0xFFFFFFFFull);
        live = live && (s > 0.f) && (cnt < K_TOP);
        const unsigned long long mw = (v < 64) ? m01 : ((v < 128) ? m23 : m4);
        const bool rated = (mw >> (v & 63)) & 1ull;
        if (live && rated) {
            const float q  = __ldg(qcol + (size_t)v * I_DIM);
            const float av = __ldg(arow + v);
            S += s;
            P += s * (q - av);
            cnt++;
        }
    }

    // Rare slow path: walk exceeded PREFETCH entries.
    if (live && cnt < K_TOP) {
        for (int k = PREFETCH; k < U_DIM && cnt < K_TOP; k++) {
            const unsigned long long ek = __ldg(srt + k);
            const float s = __uint_as_float((unsigned)(ek >> 32));
            if (s <= 0.f) break;
            const int v = (int)(ek & 0xFFFFFFFFull);
            const unsigned long long mw = (v < 64) ? m01 : ((v < 128) ? m23 : m4);
            if ((mw >> (v & 63)) & 1ull) {
                const float q  = __ldg(qcol + (size_t)v * I_DIM);
                const float av = __ldg(arow + v);
                S += s;
                P += s * (q - av);
                cnt++;
            }
        }
    }

    const float avg_u = __ldg(arow + u);
    out[b] = avg_u + P / (S + 1e-8f);
}

// ---------------------------------------------------------------------------
extern "C" void kernel_launch(void* const* d_in, const int* in_sizes, int n_in,
                              void* d_out, int out_size) {
    const float* qos      = (const float*)d_in[0];  // [T,U,I]
    const float* user_avg = (const float*)d_in[1];  // [T,U]
    const float* sim      = (const float*)d_in[2];  // [U,U]
    const int*   user_id  = (const int*)d_in[3];    // [B]
    const int*   item_id  = (const int*)d_in[4];    // [B]
    const int*   time_id  = (const int*)d_in[5];    // [B]
    float* out = (float*)d_out;

    dim3 gridA((ITEMS4 + 127) / 128, T_DIM, MASK_WORDS);   // 9 x 64 x 5 = 2880 CTAs
    mask_kernel<<<gridA, 128>>>((const float4*)qos);

    sort_kernel<<<U_DIM, 160>>>(sim);

    predict_kernel<<<(B_DIM + 127) / 128, 128>>>(qos, user_avg,
                                                 user_id, item_id, time_id, out);
}

// round 8
// speedup vs baseline: 1.3088x; 1.1426x over previous
#include <cuda_runtime.h>
#include <cstdint>

#define T_DIM 64
#define U_DIM 142
#define I_DIM 4500
#define ITEMS4 (I_DIM / 4)     // 1125 exact
#define B_DIM 16384
#define K_TOP 10
#define MASK_WORDS 5           // ceil(142/32)
#define PREFETCH 24            // sorted entries prefetched per element

#define MASK_X 9               // ceil(1125/128)
#define MASK_CTAS (MASK_X * T_DIM * MASK_WORDS)   // 2880

// Planar rated-bitmask: g_maskp[w][t*I + i]. 5 x 288000 x 4B = 5.76 MB.
__device__ uint32_t g_maskp[MASK_WORDS][(size_t)T_DIM * I_DIM];
// Per-user argsort of sim row, descending, tie -> lower index first.
// Entry: (float bits << 32) | user index. 161 KB (L2-resident).
__device__ unsigned long long g_sorted[U_DIM * U_DIM];

// ---------------------------------------------------------------------------
// Fused Phase A: mask stream (2880 CTAs) + sim-row argsort (142 CTAs).
// Sort CTAs are pure compute and hide under the DRAM-bound mask stream.
// ---------------------------------------------------------------------------
__global__ __launch_bounds__(128) void prep_kernel(const float4* __restrict__ qos4,
                                                   const float*  __restrict__ sim)
{
    __shared__ float row[U_DIM];

    if (blockIdx.x < MASK_CTAS) {
        // ---- mask part ----
        const int id = blockIdx.x;
        const int w  = id / (MASK_X * T_DIM);
        const int r  = id % (MASK_X * T_DIM);
        const int t  = r / MASK_X;
        const int x  = r % MASK_X;
        const int i4 = x * 128 + threadIdx.x;
        if (i4 >= ITEMS4) return;

        const float4* base = qos4 + ((size_t)t * U_DIM + w * 32) * ITEMS4 + i4;
        const int nb = (w < 4) ? 32 : (U_DIM - 128);

        uint32_t m0 = 0, m1 = 0, m2 = 0, m3 = 0;
        #pragma unroll
        for (int vb = 0; vb < 32; vb++) {
            if (vb < nb) {
                const float4 q = __ldcs(base + (size_t)vb * ITEMS4);  // evict-first
                const uint32_t bit = 1u << vb;
                if (q.x > 0.f) m0 |= bit;
                if (q.y > 0.f) m1 |= bit;
                if (q.z > 0.f) m2 |= bit;
                if (q.w > 0.f) m3 |= bit;
            }
        }
        *(uint4*)(&g_maskp[w][(size_t)t * I_DIM + 4 * (size_t)i4]) =
            make_uint4(m0, m1, m2, m3);
    } else {
        // ---- sort part: one CTA per user u ----
        const int u = blockIdx.x - MASK_CTAS;
        const int tid = threadIdx.x;
        if (tid < U_DIM) row[tid] = sim[u * U_DIM + tid];
        if (tid + 128 < U_DIM) row[tid + 128] = sim[u * U_DIM + tid + 128];
        __syncthreads();

        #pragma unroll
        for (int half = 0; half < 2; half++) {
            const int v = tid + half * 128;
            if (v < U_DIM) {
                const float sv = row[v];
                int rank = 0;
                #pragma unroll 2
                for (int q = 0; q < U_DIM; q++) {
                    const float sq = row[q];
                    rank += (sq > sv) || (sq == sv && q < v);
                }
                g_sorted[u * U_DIM + rank] =
                    ((unsigned long long)__float_as_uint(sv) << 32) | (unsigned)v;
            }
        }
    }
}

// ---------------------------------------------------------------------------
// Phase B: one thread per batch element. All gathers for rated entries in the
// prefetch window are issued unconditionally (independent of the sequential
// take-count) -> full MLP; then a register-only pass applies the exact
// "first <=10 rated while sim>0" selection.
// ---------------------------------------------------------------------------
__global__ __launch_bounds__(128) void predict_kernel(
    const float* __restrict__ qos,
    const float* __restrict__ user_avg,
    const int*   __restrict__ user_id,
    const int*   __restrict__ item_id,
    const int*   __restrict__ time_id,
    float*       __restrict__ out)
{
    const int b = blockIdx.x * blockDim.x + threadIdx.x;
    if (b >= B_DIM) return;

    const int t  = time_id[b];
    const int u  = user_id[b];
    const int it = item_id[b];

    const size_t ti = (size_t)t * I_DIM + it;
    const unsigned long long m01 =
        (unsigned long long)g_maskp[0][ti] | ((unsigned long long)g_maskp[1][ti] << 32);
    const unsigned long long m23 =
        (unsigned long long)g_maskp[2][ti] | ((unsigned long long)g_maskp[3][ti] << 32);
    const unsigned long long m4 = (unsigned long long)g_maskp[4][ti];

    const unsigned long long* srt = g_sorted + u * U_DIM;
    const float* qcol = qos + (size_t)t * U_DIM * I_DIM + it;
    const float* arow = user_avg + t * U_DIM;

    // Burst-load sorted entries (L2-resident, 12 independent 16B loads).
    unsigned long long e[PREFETCH];
    #pragma unroll
    for (int k = 0; k < PREFETCH; k += 2) {
        const ulonglong2 p = __ldg((const ulonglong2*)(srt + k));
        e[k] = p.x; e[k + 1] = p.y;
    }

    // Decode + unconditional gathers for rated entries (independent loads).
    float sve[PREFETCH], qv[PREFETCH], av[PREFETCH];
    bool  rd[PREFETCH];
    #pragma unroll
    for (int k = 0; k < PREFETCH; k++) {
        const float s = __uint_as_float((unsigned)(e[k] >> 32));
        const int   v = (int)(e[k] & 0xFFFFFFFFull);
        const unsigned long long mw = (v < 64) ? m01 : ((v < 128) ? m23 : m4);
        const bool rated = (mw >> (v & 63)) & 1ull;
        sve[k] = s;
        rd[k]  = rated;
        qv[k]  = rated ? __ldg(qcol + (size_t)v * I_DIM) : 0.f;   // DRAM gather
        av[k]  = rated ? __ldg(arow + v) : 0.f;                   // L1/L2 hit
    }

    // Register-only sequential selection (exact reference semantics).
    float S = 0.f, P = 0.f;
    int cnt = 0;
    #pragma unroll
    for (int k = 0; k < PREFETCH; k++) {
        const bool take = rd[k] && (sve[k] > 0.f) && (cnt < K_TOP);
        if (take) {
            S += sve[k];
            P += sve[k] * (qv[k] - av[k]);
            cnt++;
        }
    }

    // Rare slow path: window exhausted with sims still positive.
    if (cnt < K_TOP && sve[PREFETCH - 1] > 0.f) {
        for (int k = PREFETCH; k < U_DIM && cnt < K_TOP; k++) {
            const unsigned long long ek = __ldg(srt + k);
            const float s = __uint_as_float((unsigned)(ek >> 32));
            if (s <= 0.f) break;
            const int v = (int)(ek & 0xFFFFFFFFull);
            const unsigned long long mw = (v < 64) ? m01 : ((v < 128) ? m23 : m4);
            if ((mw >> (v & 63)) & 1ull) {
                const float q  = __ldg(qcol + (size_t)v * I_DIM);
                const float a  = __ldg(arow + v);
                S += s;
                P += s * (q - a);
                cnt++;
            }
        }
    }

    const float avg_u = __ldg(arow + u);
    out[b] = avg_u + P / (S + 1e-8f);
}

// ---------------------------------------------------------------------------
extern "C" void kernel_launch(void* const* d_in, const int* in_sizes, int n_in,
                              void* d_out, int out_size) {
    const float* qos      = (const float*)d_in[0];  // [T,U,I]
    const float* user_avg = (const float*)d_in[1];  // [T,U]
    const float* sim      = (const float*)d_in[2];  // [U,U]
    const int*   user_id  = (const int*)d_in[3];    // [B]
    const int*   item_id  = (const int*)d_in[4];    // [B]
    const int*   time_id  = (const int*)d_in[5];    // [B]
    float* out = (float*)d_out;

    prep_kernel<<<MASK_CTAS + U_DIM, 128>>>((const float4*)qos, sim);

    predict_kernel<<<(B_DIM + 127) / 128, 128>>>(qos, user_avg,
                                                 user_id, item_id, time_id, out);
}

// round 9
// speedup vs baseline: 1.4523x; 1.1097x over previous
#include <cuda_runtime.h>
#include <cstdint>

#define T_DIM 64
#define U_DIM 142
#define I_DIM 4500
#define ITEMS4 (I_DIM / 4)     // 1125 exact
#define B_DIM 16384
#define K_TOP 10
#define MASK_WORDS 5           // ceil(142/32)
#define LANES_PER_B 4
#define ENT_PER_LANE 6
#define PREFETCH (LANES_PER_B * ENT_PER_LANE)   // 24

#define MASK_X 9               // ceil(1125/128)
#define MASK_CTAS (MASK_X * T_DIM * MASK_WORDS)   // 2880

// Planar rated-bitmask: g_maskp[w][t*I + i]. 5 x 288000 x 4B = 5.76 MB.
__device__ uint32_t g_maskp[MASK_WORDS][(size_t)T_DIM * I_DIM];
// Per-user argsort of sim row, descending, tie -> lower index first.
// Entry: (float bits << 32) | user index. 161 KB (L2-resident).
__device__ unsigned long long g_sorted[U_DIM * U_DIM];

// ---------------------------------------------------------------------------
// Fused Phase A: mask stream (2880 CTAs) + sim-row argsort (142 CTAs).
// ---------------------------------------------------------------------------
__global__ __launch_bounds__(128) void prep_kernel(const float4* __restrict__ qos4,
                                                   const float*  __restrict__ sim)
{
    __shared__ float row[U_DIM];

    if (blockIdx.x < MASK_CTAS) {
        const int id = blockIdx.x;
        const int w  = id / (MASK_X * T_DIM);
        const int r  = id % (MASK_X * T_DIM);
        const int t  = r / MASK_X;
        const int x  = r % MASK_X;
        const int i4 = x * 128 + threadIdx.x;
        if (i4 >= ITEMS4) return;

        const float4* base = qos4 + ((size_t)t * U_DIM + w * 32) * ITEMS4 + i4;
        const int nb = (w < 4) ? 32 : (U_DIM - 128);

        uint32_t m0 = 0, m1 = 0, m2 = 0, m3 = 0;
        #pragma unroll
        for (int vb = 0; vb < 32; vb++) {
            if (vb < nb) {
                const float4 q = __ldcs(base + (size_t)vb * ITEMS4);  // evict-first
                const uint32_t bit = 1u << vb;
                if (q.x > 0.f) m0 |= bit;
                if (q.y > 0.f) m1 |= bit;
                if (q.z > 0.f) m2 |= bit;
                if (q.w > 0.f) m3 |= bit;
            }
        }
        *(uint4*)(&g_maskp[w][(size_t)t * I_DIM + 4 * (size_t)i4]) =
            make_uint4(m0, m1, m2, m3);
    } else {
        const int u = blockIdx.x - MASK_CTAS;
        const int tid = threadIdx.x;
        if (tid < U_DIM) row[tid] = sim[u * U_DIM + tid];
        if (tid + 128 < U_DIM) row[tid + 128] = sim[u * U_DIM + tid + 128];
        __syncthreads();

        #pragma unroll
        for (int half = 0; half < 2; half++) {
            const int v = tid + half * 128;
            if (v < U_DIM) {
                const float sv = row[v];
                int rank = 0;
                #pragma unroll 2
                for (int q = 0; q < U_DIM; q++) {
                    const float sq = row[q];
                    rank += (sq > sv) || (sq == sv && q < v);
                }
                g_sorted[u * U_DIM + rank] =
                    ((unsigned long long)__float_as_uint(sv) << 32) | (unsigned)v;
            }
        }
    }
}

// ---------------------------------------------------------------------------
// Phase B: FOUR threads per batch element (rank-filter selection).
// Taken set = first K_TOP entries with (rated && sim>0) in descending order;
// eligibility is count-independent -> parallel prefix across the 4 lanes.
// ---------------------------------------------------------------------------
__global__ __launch_bounds__(128) void predict_kernel(
    const float* __restrict__ qos,
    const float* __restrict__ user_avg,
    const int*   __restrict__ user_id,
    const int*   __restrict__ item_id,
    const int*   __restrict__ time_id,
    float*       __restrict__ out)
{
    const int gtid = blockIdx.x * blockDim.x + threadIdx.x;
    const int b = gtid >> 2;          // batch element
    const int l = gtid & 3;           // lane-in-group
    if (b >= B_DIM) return;

    const int t  = time_id[b];
    const int u  = user_id[b];
    const int it = item_id[b];

    const size_t ti = (size_t)t * I_DIM + it;
    const unsigned long long m01 =
        (unsigned long long)g_maskp[0][ti] | ((unsigned long long)g_maskp[1][ti] << 32);
    const unsigned long long m23 =
        (unsigned long long)g_maskp[2][ti] | ((unsigned long long)g_maskp[3][ti] << 32);
    const unsigned long long m4 = (unsigned long long)g_maskp[4][ti];

    const unsigned long long* srt = g_sorted + u * U_DIM;
    const float* qcol = qos + (size_t)t * U_DIM * I_DIM + it;
    const float* arow = user_avg + t * U_DIM;

    // My 6 window entries (base offset 48*l bytes -> 16B aligned).
    unsigned long long e[ENT_PER_LANE];
    #pragma unroll
    for (int k = 0; k < ENT_PER_LANE; k += 2) {
        const ulonglong2 p = __ldg((const ulonglong2*)(srt + l * ENT_PER_LANE + k));
        e[k] = p.x; e[k + 1] = p.y;
    }

    // Decode + unconditional gathers for rated entries (independent loads).
    float sve[ENT_PER_LANE], qv[ENT_PER_LANE], av[ENT_PER_LANE];
    bool  elig[ENT_PER_LANE];
    int local_cnt = 0;
    #pragma unroll
    for (int k = 0; k < ENT_PER_LANE; k++) {
        const float s = __uint_as_float((unsigned)(e[k] >> 32));
        const int   v = (int)(e[k] & 0xFFFFFFFFull);
        const unsigned long long mw = (v < 64) ? m01 : ((v < 128) ? m23 : m4);
        const bool rated = (mw >> (v & 63)) & 1ull;
        sve[k]  = s;
        elig[k] = rated && (s > 0.f);
        local_cnt += elig[k];
        qv[k] = rated ? __ldg(qcol + (size_t)v * I_DIM) : 0.f;   // DRAM gather
        av[k] = rated ? __ldg(arow + v) : 0.f;                   // cache hit
    }

    // Group-exclusive prefix of eligible counts (groups are lane-aligned).
    const int wl   = threadIdx.x & 31;
    const int base = wl & ~3;
    const int c0 = __shfl_sync(0xFFFFFFFFu, local_cnt, base + 0);
    const int c1 = __shfl_sync(0xFFFFFFFFu, local_cnt, base + 1);
    const int c2 = __shfl_sync(0xFFFFFFFFu, local_cnt, base + 2);
    const int c3 = __shfl_sync(0xFFFFFFFFu, local_cnt, base + 3);
    int rank = (l > 0 ? c0 : 0) + (l > 1 ? c1 : 0) + (l > 2 ? c2 : 0);
    const int total_elig = c0 + c1 + c2 + c3;

    // Take entries with global eligible-rank < K_TOP.
    float S = 0.f, P = 0.f;
    #pragma unroll
    for (int k = 0; k < ENT_PER_LANE; k++) {
        if (elig[k]) {
            if (rank < K_TOP) {
                S += sve[k];
                P += sve[k] * (qv[k] - av[k]);
            }
            rank++;
        }
    }

    // Reduce (S, P) across the 4 group lanes.
    #pragma unroll
    for (int o = 1; o < 4; o <<= 1) {
        S += __shfl_xor_sync(0xFFFFFFFFu, S, o);
        P += __shfl_xor_sync(0xFFFFFFFFu, P, o);
    }

    // s of the last window entry (lane 3, k=5) -> broadcast for tail test.
    const float s_last = __shfl_sync(0xFFFFFFFFu, sve[ENT_PER_LANE - 1], base + 3);

    if (l == 0) {
        // Rare tail: window exhausted with <K eligible and sims still positive.
        if (total_elig < K_TOP && s_last > 0.f) {
            int cnt = total_elig;
            for (int k = PREFETCH; k < U_DIM && cnt < K_TOP; k++) {
                const unsigned long long ek = __ldg(srt + k);
                const float s = __uint_as_float((unsigned)(ek >> 32));
                if (s <= 0.f) break;
                const int v = (int)(ek & 0xFFFFFFFFull);
                const unsigned long long mw = (v < 64) ? m01 : ((v < 128) ? m23 : m4);
                if ((mw >> (v & 63)) & 1ull) {
                    const float q = __ldg(qcol + (size_t)v * I_DIM);
                    const float a = __ldg(arow + v);
                    S += s;
                    P += s * (q - a);
                    cnt++;
                }
            }
        }
        const float avg_u = __ldg(arow + u);
        out[b] = avg_u + P / (S + 1e-8f);
    }
}

// ---------------------------------------------------------------------------
extern "C" void kernel_launch(void* const* d_in, const int* in_sizes, int n_in,
                              void* d_out, int out_size) {
    const float* qos      = (const float*)d_in[0];  // [T,U,I]
    const float* user_avg = (const float*)d_in[1];  // [T,U]
    const float* sim      = (const float*)d_in[2];  // [U,U]
    const int*   user_id  = (const int*)d_in[3];    // [B]
    const int*   item_id  = (const int*)d_in[4];    // [B]
    const int*   time_id  = (const int*)d_in[5];    // [B]
    float* out = (float*)d_out;

    prep_kernel<<<MASK_CTAS + U_DIM, 128>>>((const float4*)qos, sim);

    predict_kernel<<<(B_DIM * LANES_PER_B + 127) / 128, 128>>>(
        qos, user_avg, user_id, item_id, time_id, out);
}

// round 12
// speedup vs baseline: 4.0375x; 2.7800x over previous
#include <cuda_runtime.h>
#include <cstdint>

#define T_DIM 64
#define U_DIM 142
#define I_DIM 4500
#define B_DIM 16384
#define K_TOP 10
#define LANES_PER_B 8
#define ENT_PER_LANE 3
#define WINDOW (LANES_PER_B * ENT_PER_LANE)   // 24

// Per-user argsort of sim row, descending, tie -> lower index first.
// Entry: (float bits << 32) | user index. 161 KB (L2-resident).
__device__ unsigned long long g_sorted[U_DIM * U_DIM];

// ---------------------------------------------------------------------------
// Argsort of each sim row (descending, stable by index). One CTA per user.
// ---------------------------------------------------------------------------
__global__ __launch_bounds__(160) void sort_kernel(const float* __restrict__ sim)
{
    const int u = blockIdx.x;
    const int v = threadIdx.x;
    __shared__ float row[U_DIM];
    if (v < U_DIM) row[v] = sim[u * U_DIM + v];
    __syncthreads();
    if (v >= U_DIM) return;

    const float sv = row[v];
    int rank = 0;
    #pragma unroll 2
    for (int w = 0; w < U_DIM; w++) {
        const float sw = row[w];
        rank += (sw > sv) || (sw == sv && w < v);
    }
    g_sorted[u * U_DIM + rank] =
        ((unsigned long long)__float_as_uint(sv) << 32) | (unsigned)v;
}

// ---------------------------------------------------------------------------
// Predict: EIGHT threads per batch element. Probe qos directly in descending
// sim order — the gathered value IS the rated test (q>0) and the prediction
// term. Taken set = first K_TOP entries with (q>0 && s>0): eligibility is
// count-independent -> parallel rank filter via 8-lane prefix sum.
// ---------------------------------------------------------------------------
__global__ __launch_bounds__(256) void predict_kernel(
    const float* __restrict__ qos,
    const float* __restrict__ user_avg,
    const int*   __restrict__ user_id,
    const int*   __restrict__ item_id,
    const int*   __restrict__ time_id,
    float*       __restrict__ out)
{
    const int gtid = blockIdx.x * blockDim.x + threadIdx.x;
    const int b = gtid >> 3;          // batch element
    const int l = gtid & 7;           // lane-in-group
    if (b >= B_DIM) return;

    const int t  = time_id[b];
    const int u  = user_id[b];
    const int it = item_id[b];

    const unsigned long long* srt = g_sorted + u * U_DIM;
    const float* qcol = qos + (size_t)t * U_DIM * I_DIM + it;
    const float* arow = user_avg + t * U_DIM;

    // My 3 sorted entries (L2-resident), then 3 independent qos DRAM gathers
    // + 3 cache-resident avg loads. All loads in the group are independent.
    float sve[ENT_PER_LANE], qv[ENT_PER_LANE], av[ENT_PER_LANE];
    bool  elig[ENT_PER_LANE];
    int local_cnt = 0;
    #pragma unroll
    for (int k = 0; k < ENT_PER_LANE; k++) {
        const unsigned long long ek = __ldg(srt + l * ENT_PER_LANE + k);
        const float s = __uint_as_float((unsigned)(ek >> 32));
        const int   v = (int)(ek & 0xFFFFFFFFull);
        const float q = __ldg(qcol + (size_t)v * I_DIM);   // DRAM gather
        const float a = __ldg(arow + v);                   // L1/L2 hit
        sve[k]  = s;
        qv[k]   = q;
        av[k]   = a;
        elig[k] = (q > 0.f) && (s > 0.f);
        local_cnt += elig[k];
    }

    // Exclusive prefix of eligible counts across the 8 group lanes.
    const unsigned full = 0xFFFFFFFFu;
    const int wl = threadIdx.x & 31;
    int inc = local_cnt;
    #pragma unroll
    for (int o = 1; o < LANES_PER_B; o <<= 1) {
        const int x = __shfl_up_sync(full, inc, o);
        if ((wl & (LANES_PER_B - 1)) >= o) inc += x;
    }
    int rank = inc - local_cnt;
    const int base = wl & ~(LANES_PER_B - 1);
    const int total_elig = __shfl_sync(full, inc, base + LANES_PER_B - 1);

    // Take entries with global eligible-rank < K_TOP.
    float S = 0.f, P = 0.f;
    #pragma unroll
    for (int k = 0; k < ENT_PER_LANE; k++) {
        if (elig[k]) {
            if (rank < K_TOP) {
                S += sve[k];
                P += sve[k] * (qv[k] - av[k]);
            }
            rank++;
        }
    }

    // Reduce (S, P) across the 8 group lanes (stays within aligned group).
    #pragma unroll
    for (int o = 1; o < LANES_PER_B; o <<= 1) {
        S += __shfl_xor_sync(full, S, o);
        P += __shfl_xor_sync(full, P, o);
    }

    // sim of the last window entry for the tail test (lane 7, k=2).
    const float s_last = __shfl_sync(full, sve[ENT_PER_LANE - 1],
                                     base + LANES_PER_B - 1);

    if (l == 0) {
        // Rare tail (~1e-3): window had <K eligible and sims still positive.
        if (total_elig < K_TOP && s_last > 0.f) {
            int cnt = total_elig;
            for (int k = WINDOW; k < U_DIM && cnt < K_TOP; k++) {
                const unsigned long long ek = __ldg(srt + k);
                const float s = __uint_as_float((unsigned)(ek >> 32));
                if (s <= 0.f) break;
                const int v = (int)(ek & 0xFFFFFFFFull);
                const float q = __ldg(qcol + (size_t)v * I_DIM);
                if (q > 0.f) {
                    S += s;
                    P += s * (q - __ldg(arow + v));
                    cnt++;
                }
            }
        }
        const float avg_u = __ldg(arow + u);
        out[b] = avg_u + P / (S + 1e-8f);
    }
}

// ---------------------------------------------------------------------------
extern "C" void kernel_launch(void* const* d_in, const int* in_sizes, int n_in,
                              void* d_out, int out_size) {
    const float* qos      = (const float*)d_in[0];  // [T,U,I]
    const float* user_avg = (const float*)d_in[1];  // [T,U]
    const float* sim      = (const float*)d_in[2];  // [U,U]
    const int*   user_id  = (const int*)d_in[3];    // [B]
    const int*   item_id  = (const int*)d_in[4];    // [B]
    const int*   time_id  = (const int*)d_in[5];    // [B]
    float* out = (float*)d_out;

    sort_kernel<<<U_DIM, 160>>>(sim);

    predict_kernel<<<(B_DIM * LANES_PER_B) / 256, 256>>>(
        qos, user_avg, user_id, item_id, time_id, out);
}